// round 13
// baseline (speedup 1.0000x reference)
#include <cuda_runtime.h>
#include <cuda_fp16.h>
#include <cstdint>
#include <math.h>

#define BSZ 16
#define NC  1024
#define NT  2048
#define NTT (BSZ*NT)
#define XD  8
#define HID 256
#define HH  128
#define DD  384
#define NE  4

// ---------------- scratch ----------------
__device__ float g_enc3[BSZ*HID];
__device__ float g_gd [(size_t)NTT*NE];

// activations: single fp16
__device__ __half g_z  [(size_t)NTT*512];
__device__ __half g_fh [(size_t)NTT*HH];
__device__ __half g_zd [(size_t)NTT*DD];
__device__ __half g_zd2[(size_t)NTT*DD];
__device__ __half g_h1 [(size_t)NTT*HID];
__device__ __half g_h2 [(size_t)NTT*HID];

// weights: single fp16, pre-transposed to [N,K] K-major
__device__ __half g_wf1[128*512];
__device__ __half g_wf2[256*128];
__device__ __half g_wm [4*384*384];
__device__ __half g_wd1[256*384];
__device__ __half g_wd2[256*256];

// ---------------- weight prep: all 5 tensors in one launch ----------------
struct PrepDesc { const float* W; __half* O; int K; int N; int total; };

__global__ __launch_bounds__(256) void prep_all(
    PrepDesc d0, PrepDesc d1, PrepDesc d2, PrepDesc d3, PrepDesc d4)
{
    PrepDesc d;
    switch (blockIdx.y) {
        case 0: d = d0; break;
        case 1: d = d1; break;
        case 2: d = d2; break;
        case 3: d = d3; break;
        default: d = d4; break;
    }
    int KN = d.K * d.N;
    for (int idx = blockIdx.x*256 + threadIdx.x; idx < d.total; idx += gridDim.x*256) {
        int e = idx / KN, rem = idx - e*KN;
        int n = rem / d.K, k = rem - n*d.K;
        d.O[idx] = __float2half_rn(d.W[(size_t)e*KN + (size_t)k*d.N + n]);
    }
}

// ---------------- mma.sync helpers ----------------
__device__ __forceinline__ uint32_t smem_u32(const void* p) {
    uint32_t a;
    asm("{ .reg .u64 t; cvta.to.shared.u64 t, %1; cvt.u32.u64 %0, t; }" : "=r"(a) : "l"(p));
    return a;
}
__device__ __forceinline__ void ldm_x4(uint32_t* r, uint32_t addr) {
    asm volatile("ldmatrix.sync.aligned.m8n8.x4.shared.b16 {%0,%1,%2,%3}, [%4];"
        : "=r"(r[0]), "=r"(r[1]), "=r"(r[2]), "=r"(r[3]) : "r"(addr));
}
__device__ __forceinline__ void mma16816(float* d, const uint32_t* a, const uint32_t* b) {
    asm volatile(
        "mma.sync.aligned.m16n8k16.row.col.f32.f16.f16.f32 "
        "{%0,%1,%2,%3}, {%4,%5,%6,%7}, {%8,%9}, {%0,%1,%2,%3};"
        : "+f"(d[0]), "+f"(d[1]), "+f"(d[2]), "+f"(d[3])
        : "r"(a[0]), "r"(a[1]), "r"(a[2]), "r"(a[3]), "r"(b[0]), "r"(b[1]));
}
__device__ __forceinline__ void cp16(uint32_t dst, const void* src) {
    asm volatile("cp.async.ca.shared.global [%0], [%1], 16;" :: "r"(dst), "l"(src));
}
__device__ __forceinline__ void cp_commit() { asm volatile("cp.async.commit_group;"); }
__device__ __forceinline__ void cp_wait0()  { asm volatile("cp.async.wait_group 0;"); }

// smem: fp16, BK=64, row stride 72 (144B; +4 banks/row -> ldmatrix conflict-free)
// CTA tile 128(M) x 64(N); A tile 128x64 (1024 chunks), B tile 64x64 (512 chunks)
#define LDS    72
#define ATILEB 18432            // 128*72*2
#define BTILEB 9216             // 64*72*2
#define OFF_A(s) ((s)*ATILEB)
#define OFF_B(s) (36864 + (s)*BTILEB)
#define SMEM_GEMM  55296

// C[M,Nfull](@ldc,coff) fp16 = act( rowscale(A) @ B^T + bias_eff )
// 8 warps as 4(M) x 2(N), warp tile 32x32. gate!=null: A rows scaled per expert
// (LDG+scale+STS), acc over experts, gated bias. Non-gated: pure cp.async.
__global__ __launch_bounds__(256, 3) void mma_gemm(
    const __half* __restrict__ A, const __half* __restrict__ Bw,
    const float* __restrict__ bias, const float* __restrict__ gate,
    __half* __restrict__ C,
    int K, int ldc, int coff, int nexp, int relu)
{
    extern __shared__ char smc[];
    __shared__ float sbias[NE*64];
    uint32_t smb = smem_u32(smc);
    int tid = threadIdx.x;
    int lane = tid & 31, warp = tid >> 5;
    int wm = warp >> 1, wn = warp & 1;          // 4x2 warps: 32x32 warp tile
    int m0 = blockIdx.x * 128, n0 = blockIdx.y * 64;
    int Nfull = gridDim.y * 64;
    size_t bstride = (size_t)Nfull * K;

    for (int i = tid; i < nexp*64; i += 256)
        sbias[i] = bias[(size_t)(i >> 6) * Nfull + n0 + (i & 63)];

    float acc[2][4][4];
    #pragma unroll
    for (int mi = 0; mi < 2; mi++)
        #pragma unroll
        for (int ni = 0; ni < 4; ni++)
            #pragma unroll
            for (int q = 0; q < 4; q++) acc[mi][ni][q] = 0.f;

    const int tiles = K >> 6;                   // BK = 64
    const int T = nexp * tiles;

    // A: 128 rows x 8 chunk-cols = 1024 chunks -> 4 per thread
    int arow[4], acol[4];
    #pragma unroll
    for (int i = 0; i < 4; i++) {
        int c = tid + i*256;
        arow[i] = c >> 3; acol[i] = (c & 7) << 3;
    }
    // B: 64 rows x 8 chunk-cols = 512 chunks -> 2 per thread
    int brow[2], bcol[2];
    #pragma unroll
    for (int i = 0; i < 2; i++) {
        int c = tid + i*256;
        brow[i] = c >> 3; bcol[i] = (c & 7) << 3;
    }

    uint4 ar[4]; float gv[4];

    auto load_async = [&](int s, int it2) {
        int e = it2 / tiles, k0 = (it2 - e*tiles) << 6;
        const __half* Bh = Bw + (size_t)e * bstride;
        #pragma unroll
        for (int i = 0; i < 2; i++)
            cp16(smb + OFF_B(s) + (uint32_t)(brow[i] * LDS + bcol[i]) * 2,
                 &Bh[(size_t)(n0 + brow[i]) * K + k0 + bcol[i]]);
        if (!gate) {
            #pragma unroll
            for (int i = 0; i < 4; i++)
                cp16(smb + OFF_A(s) + (uint32_t)(arow[i] * LDS + acol[i]) * 2,
                     &A[(size_t)(m0 + arow[i]) * K + k0 + acol[i]]);
        }
        cp_commit();
    };
    auto load_a_regs = [&](int it2) {
        int e = it2 / tiles, k0 = (it2 - e*tiles) << 6;
        #pragma unroll
        for (int i = 0; i < 4; i++) {
            ar[i] = *(const uint4*)&A[(size_t)(m0 + arow[i]) * K + k0 + acol[i]];
            gv[i] = gate[(size_t)(m0 + arow[i]) * 4 + e];
        }
    };
    auto store_a = [&](int s) {
        #pragma unroll
        for (int i = 0; i < 4; i++) {
            const uint32_t* pp = (const uint32_t*)&ar[i];
            uint32_t o[4];
            #pragma unroll
            for (int q = 0; q < 4; q++) {
                __half2 h2 = *(const __half2*)&pp[q];
                float2 f = __half22float2(h2);
                __half2 r = __floats2half2_rn(f.x * gv[i], f.y * gv[i]);
                o[q] = *(const uint32_t*)&r;
            }
            uint32_t d = (uint32_t)(arow[i] * LDS + acol[i]) * 2;
            *(uint4*)(smc + OFF_A(s) + d) = make_uint4(o[0], o[1], o[2], o[3]);
        }
    };

    // prologue
    load_async(0, 0);
    if (gate) { load_a_regs(0); store_a(0); }
    cp_wait0();
    __syncthreads();

    for (int it = 0; it < T; it++) {
        int s = it & 1, ns = s ^ 1;
        if (it + 1 < T) {
            load_async(ns, it + 1);
            if (gate) load_a_regs(it + 1);
        }

        uint32_t aS = smb + OFF_A(s), bS = smb + OFF_B(s);
        #pragma unroll
        for (int ks = 0; ks < 4; ks++) {          // 4 x K16 within BK=64
            uint32_t bh[4][2], r4[4];
            #pragma unroll
            for (int np = 0; np < 2; np++) {
                uint32_t off = (uint32_t)((wn*32 + np*16 + (lane & 15)) * LDS
                                          + ks*16 + (lane >> 4)*8) * 2;
                ldm_x4(r4, bS + off);
                bh[np*2+0][0] = r4[0]; bh[np*2+0][1] = r4[2];
                bh[np*2+1][0] = r4[1]; bh[np*2+1][1] = r4[3];
            }
            uint32_t ah[2][4];
            #pragma unroll
            for (int mi = 0; mi < 2; mi++) {
                uint32_t off = (uint32_t)((wm*32 + mi*16 + (lane & 15)) * LDS
                                          + ks*16 + (lane >> 4)*8) * 2;
                ldm_x4(ah[mi], aS + off);
            }
            #pragma unroll
            for (int mi = 0; mi < 2; mi++)
                #pragma unroll
                for (int ni = 0; ni < 4; ni++)
                    mma16816(acc[mi][ni], ah[mi], bh[ni]);
        }
        if (it + 1 < T) {
            if (gate) store_a(ns);
            cp_wait0();
        }
        __syncthreads();
    }

    // epilogue: fp16 C, gated bias
    #pragma unroll
    for (int mi = 0; mi < 2; mi++) {
        #pragma unroll
        for (int sub = 0; sub < 2; sub++) {
            int row = m0 + wm*32 + mi*16 + (lane >> 2) + sub*8;
            float4 g4 = make_float4(0.f, 0.f, 0.f, 0.f);
            if (gate) g4 = *(const float4*)&gate[(size_t)row * 4];
            #pragma unroll
            for (int ni = 0; ni < 4; ni++) {
                int cl = wn*32 + ni*8 + (lane & 3)*2;
                float be0, be1;
                if (gate) {
                    be0 = g4.x*sbias[cl]    + g4.y*sbias[64+cl]
                        + g4.z*sbias[128+cl] + g4.w*sbias[192+cl];
                    be1 = g4.x*sbias[cl+1]    + g4.y*sbias[64+cl+1]
                        + g4.z*sbias[128+cl+1] + g4.w*sbias[192+cl+1];
                } else { be0 = sbias[cl]; be1 = sbias[cl+1]; }
                float v0 = acc[mi][ni][sub*2+0] + be0;
                float v1 = acc[mi][ni][sub*2+1] + be1;
                if (relu) { v0 = fmaxf(v0, 0.f); v1 = fmaxf(v1, 0.f); }
                *(__half2*)&C[(size_t)row * ldc + coff + n0 + cl] = __floats2half2_rn(v0, v1);
            }
        }
    }
}

// ---------------- enc3 ----------------
__global__ __launch_bounds__(256) void enc3_kernel(
    const float* __restrict__ cx, const float* __restrict__ cy,
    const float* __restrict__ Wp, const float* __restrict__ bp,
    const float* __restrict__ Wl, const float* __restrict__ bl)
{
    __shared__ float red[256*9];
    __shared__ float h0[HID];
    int b = blockIdx.x, tid = threadIdx.x;
    float l[9];
    #pragma unroll
    for (int x = 0; x < 9; x++) l[x] = 0.f;
    for (int c = tid; c < NC; c += 256) {
        #pragma unroll
        for (int x = 0; x < XD; x++) l[x] += cx[((size_t)b*NC + c)*XD + x];
        l[8] += cy[b*NC + c];
    }
    #pragma unroll
    for (int x = 0; x < 9; x++) red[tid*9 + x] = l[x];
    __syncthreads();
    for (int s = 128; s; s >>= 1) {
        if (tid < s) {
            #pragma unroll
            for (int x = 0; x < 9; x++) red[tid*9 + x] += red[(tid+s)*9 + x];
        }
        __syncthreads();
    }
    {
        int h = tid;
        float a = bp[h];
        #pragma unroll
        for (int x = 0; x < 9; x++) a = fmaf(red[x]*(1.f/NC), Wp[x*HID + h], a);
        h0[h] = a;
    }
    __syncthreads();
    {
        int h = tid;
        float a = bl[h];
        for (int k = 0; k < HID; k++) a = fmaf(h0[k], Wl[k*HID + h], a);
        g_enc3[b*HID + h] = a;
    }
}

// ---------------- per-target encoder (writes fp16 activations) ----------------
__global__ __launch_bounds__(256) void target_kernel(
    const float* __restrict__ cx, const float* __restrict__ cy,
    const float* __restrict__ txg,
    const float* __restrict__ Wee, const float* __restrict__ bee,
    const float* __restrict__ Wge, const float* __restrict__ bge,
    const float* __restrict__ Wat, const float* __restrict__ bat)
{
    extern __shared__ float smf[];
    float* sc  = smf;
    float* sWe = sc  + NC*9;
    float* sbe = sWe + NE*9*HID;
    float* sWa = sbe + NE*HID;
    float* sba = sWa + XD*HH;
    float* sWg = sba + HH;
    float* sbg = sWg + XD*NE;

    int b  = blockIdx.x >> 4;
    int t0 = (blockIdx.x & 15) << 7;
    int tid = threadIdx.x;

    for (int i = tid; i < NC*XD; i += 256) sc[(i>>3)*9 + (i&7)] = cx[(size_t)b*NC*XD + i];
    for (int i = tid; i < NC;    i += 256) sc[i*9 + 8] = cy[b*NC + i];
    for (int i = tid; i < NE*9*HID; i += 256) sWe[i] = Wee[i];
    for (int i = tid; i < NE*HID;   i += 256) sbe[i] = bee[i];
    for (int i = tid; i < XD*HH;    i += 256) sWa[i] = Wat[i];
    if (tid < HH)    sba[tid] = bat[tid];
    if (tid < XD*NE) sWg[tid] = Wge[tid];
    if (tid < NE)    sbg[tid] = bge[tid];
    __syncthreads();

    int warp = tid >> 5, lane = tid & 31;
    for (int tt = warp; tt < 128; tt += 8) {
        int t = t0 + tt;
        size_t gt = (size_t)b*NT + t;
        float tx[XD];
        #pragma unroll
        for (int x = 0; x < XD; x++) tx[x] = txg[gt*XD + x];

        float acc[10];
        #pragma unroll
        for (int i = 0; i < 10; i++) acc[i] = 0.f;
        for (int c = lane; c < NC; c += 32) {
            const float* p = &sc[c*9];
            float d2 = 1e-12f;
            #pragma unroll
            for (int x = 0; x < XD; x++) { float d = tx[x]-p[x]; d2 = fmaf(d, d, d2); }
            float dist = d2 * __frsqrt_rn(d2);
            float w = __expf(-dist);
            acc[9] += w;
            #pragma unroll
            for (int x = 0; x < 9; x++) acc[x] = fmaf(w, p[x], acc[x]);
        }
        #pragma unroll
        for (int o = 16; o; o >>= 1) {
            #pragma unroll
            for (int i = 0; i < 10; i++) acc[i] += __shfl_xor_sync(0xffffffffu, acc[i], o);
        }
        float inv = 1.f/acc[9];
        float s[9];
        #pragma unroll
        for (int x = 0; x < 9; x++) s[x] = acc[x]*inv;

        float g[NE];
        #pragma unroll
        for (int e = 0; e < NE; e++) {
            float a = sbg[e];
            #pragma unroll
            for (int x = 0; x < XD; x++) a = fmaf(tx[x], sWg[x*NE + e], a);
            g[e] = a;
        }
        float gm = fmaxf(fmaxf(g[0],g[1]), fmaxf(g[2],g[3]));
        float gs = 0.f;
        #pragma unroll
        for (int e = 0; e < NE; e++) { g[e] = __expf(g[e]-gm); gs += g[e]; }
        float gi = 1.f/gs;
        #pragma unroll
        for (int e = 0; e < NE; e++) g[e] *= gi;

        #pragma unroll
        for (int j = 0; j < 8; j++) {
            int h = lane + 32*j;
            float o2 = 0.f;
            #pragma unroll
            for (int e = 0; e < NE; e++) {
                float a = sbe[e*HID + h];
                #pragma unroll
                for (int x = 0; x < 9; x++) a = fmaf(s[x], sWe[(e*9 + x)*HID + h], a);
                o2 = fmaf(g[e], a, o2);
            }
            g_z[gt*512 + 256 + h] = __float2half_rn(o2);
            g_z[gt*512 + h] = __float2half_rn(g_enc3[b*HID + h]);
        }
        #pragma unroll
        for (int j = 0; j < 4; j++) {
            int h = lane + 32*j;
            float a = sba[h];
            #pragma unroll
            for (int x = 0; x < XD; x++) a = fmaf(tx[x], sWa[x*HH + h], a);
            g_zd[gt*DD + h] = __float2half_rn(a);
        }
    }
}

// ---------------- decoder gate ----------------
__global__ __launch_bounds__(256) void decgate_kernel(
    const float* __restrict__ Wg, const float* __restrict__ bg)
{
    int warp = threadIdx.x >> 5, lane = threadIdx.x & 31;
    size_t gt = (size_t)blockIdx.x*8 + warp;
    float a0=0.f, a1=0.f, a2=0.f, a3=0.f;
    const float4* W4 = (const float4*)Wg;
    for (int k = lane; k < DD; k += 32) {
        float z = __half2float(g_zd[gt*DD + k]);
        float4 w = W4[k];
        a0 = fmaf(z, w.x, a0); a1 = fmaf(z, w.y, a1);
        a2 = fmaf(z, w.z, a2); a3 = fmaf(z, w.w, a3);
    }
    #pragma unroll
    for (int o = 16; o; o >>= 1) {
        a0 += __shfl_xor_sync(0xffffffffu, a0, o);
        a1 += __shfl_xor_sync(0xffffffffu, a1, o);
        a2 += __shfl_xor_sync(0xffffffffu, a2, o);
        a3 += __shfl_xor_sync(0xffffffffu, a3, o);
    }
    a0 += bg[0]; a1 += bg[1]; a2 += bg[2]; a3 += bg[3];
    float m = fmaxf(fmaxf(a0,a1), fmaxf(a2,a3));
    float e0 = __expf(a0-m), e1 = __expf(a1-m), e2 = __expf(a2-m), e3 = __expf(a3-m);
    float inv = 1.f/(e0+e1+e2+e3);
    if (lane == 0) {
        g_gd[gt*4+0] = e0*inv; g_gd[gt*4+1] = e1*inv;
        g_gd[gt*4+2] = e2*inv; g_gd[gt*4+3] = e3*inv;
    }
}

// ---------------- head ----------------
__global__ __launch_bounds__(256) void head_kernel(
    const float* __restrict__ W3, const float* __restrict__ b3, float* __restrict__ out)
{
    int warp = threadIdx.x >> 5, lane = threadIdx.x & 31;
    size_t gt = (size_t)blockIdx.x*8 + warp;
    float a0=0.f, a1=0.f;
    const float2* W2 = (const float2*)W3;
    for (int k = lane; k < HID; k += 32) {
        float h = __half2float(g_h2[gt*HID + k]);
        float2 w = W2[k];
        a0 = fmaf(h, w.x, a0); a1 = fmaf(h, w.y, a1);
    }
    #pragma unroll
    for (int o = 16; o; o >>= 1) {
        a0 += __shfl_xor_sync(0xffffffffu, a0, o);
        a1 += __shfl_xor_sync(0xffffffffu, a1, o);
    }
    if (lane == 0) {
        float mu = a0 + b3[0];
        float x  = a1 + b3[1];
        float sp = fmaxf(x, 0.f) + log1pf(__expf(-fabsf(x)));
        out[gt]       = mu;
        out[NTT + gt] = 0.1f + 0.9f*sp;
    }
}

// ---------------- Moran k-NN lag ----------------
__global__ __launch_bounds__(256) void moran_kernel(
    const float* __restrict__ txg, const float* __restrict__ tyg, float* __restrict__ out)
{
    extern __shared__ float smf[];
    float* st  = smf;
    float* sy  = st + NT*9;
    float* smu = sy + NT;
    int b  = blockIdx.x >> 4;
    int t0 = (blockIdx.x & 15) << 7;
    int tid = threadIdx.x;

    for (int i = tid; i < NT*XD; i += 256) st[(i>>3)*9 + (i&7)] = txg[(size_t)b*NT*XD + i];
    for (int i = tid; i < NT; i += 256) { sy[i] = tyg[b*NT + i]; smu[i] = out[b*NT + i]; }
    __syncthreads();
    for (int i = tid; i < NT; i += 256) {
        float n = 0.f;
        #pragma unroll
        for (int x = 0; x < XD; x++) { float v = st[i*9 + x]; n = fmaf(v, v, n); }
        st[i*9 + 8] = n;
    }
    __syncthreads();

    int warp = tid >> 5, lane = tid & 31;
    for (int tt = warp; tt < 128; tt += 8) {
        int t = t0 + tt;
        float tx[XD];
        #pragma unroll
        for (int x = 0; x < XD; x++) tx[x] = st[t*9 + x];
        float tn = st[t*9 + 8];

        float bd0=INFINITY,bd1=INFINITY,bd2=INFINITY,bd3=INFINITY,bd4=INFINITY;
        int   bi0=0,bi1=0,bi2=0,bi3=0,bi4=0;
        for (int c = lane; c < NT; c += 32) {
            if (c == t) continue;
            const float* p = &st[c*9];
            float dot = 0.f;
            #pragma unroll
            for (int x = 0; x < XD; x++) dot = fmaf(tx[x], p[x], dot);
            float d2 = tn + p[8] - 2.f*dot;
            d2 = fmaxf(d2, 0.f) + 1e-12f;
            if (d2 < bd4) {
                bd4 = d2; bi4 = c;
                if (bd4 < bd3) { float td=bd3; bd3=bd4; bd4=td; int ti=bi3; bi3=bi4; bi4=ti; }
                if (bd3 < bd2) { float td=bd2; bd2=bd3; bd3=td; int ti=bi2; bi2=bi3; bi3=ti; }
                if (bd2 < bd1) { float td=bd1; bd1=bd2; bd2=td; int ti=bi1; bi1=bi2; bi2=ti; }
                if (bd1 < bd0) { float td=bd0; bd0=bd1; bd1=td; int ti=bi0; bi0=bi1; bi1=ti; }
            }
        }
        float seld[5]; int seli[5];
        #pragma unroll
        for (int r = 0; r < 5; r++) {
            float rd = bd0; int ri = bi0; int rl = lane;
            #pragma unroll
            for (int o = 16; o; o >>= 1) {
                float od = __shfl_xor_sync(0xffffffffu, rd, o);
                int   oi = __shfl_xor_sync(0xffffffffu, ri, o);
                int   ol = __shfl_xor_sync(0xffffffffu, rl, o);
                if (od < rd || (od == rd && oi < ri)) { rd = od; ri = oi; rl = ol; }
            }
            seld[r] = rd; seli[r] = ri;
            if (lane == rl) {
                bd0=bd1; bi0=bi1; bd1=bd2; bi1=bi2; bd2=bd3; bi2=bi3;
                bd3=bd4; bi3=bi4; bd4=INFINITY; bi4=0x7fffffff;
            }
        }
        if (lane == 0) {
            float w[5], ws = 0.f;
            #pragma unroll
            for (int r = 0; r < 5; r++) { w[r] = __expf(-0.1f*sqrtf(seld[r])); ws += w[r]; }
            float inv = 1.f/ws;
            float ly = 0.f, lm = 0.f;
            #pragma unroll
            for (int r = 0; r < 5; r++) {
                float wr = w[r]*inv;
                ly = fmaf(wr, sy[seli[r]],  ly);
                lm = fmaf(wr, smu[seli[r]], lm);
            }
            size_t gt = (size_t)b*NT + t;
            out[2*(size_t)NTT + gt] = ly;
            out[3*(size_t)NTT + gt] = lm;
        }
    }
}

// ---------------- launch ----------------
extern "C" void kernel_launch(void* const* d_in, const int* in_sizes, int n_in,
                              void* d_out, int out_size)
{
    const float* cx   = (const float*)d_in[0];
    const float* cy   = (const float*)d_in[1];
    const float* txp  = (const float*)d_in[2];
    const float* typ  = (const float*)d_in[3];
    const float* Wge  = (const float*)d_in[4];
    const float* bge  = (const float*)d_in[5];
    const float* Wee  = (const float*)d_in[6];
    const float* bee  = (const float*)d_in[7];
    const float* Wp3  = (const float*)d_in[8];
    const float* bp3  = (const float*)d_in[9];
    const float* Wlin = (const float*)d_in[10];
    const float* blin = (const float*)d_in[11];
    const float* Wf1  = (const float*)d_in[12];
    const float* bf1  = (const float*)d_in[13];
    const float* Wf2  = (const float*)d_in[14];
    const float* bf2  = (const float*)d_in[15];
    const float* Wat  = (const float*)d_in[16];
    const float* bat  = (const float*)d_in[17];
    const float* Wgd  = (const float*)d_in[18];
    const float* bgd  = (const float*)d_in[19];
    const float* Wed  = (const float*)d_in[20];
    const float* bed  = (const float*)d_in[21];
    const float* Wd1  = (const float*)d_in[22];
    const float* bd1  = (const float*)d_in[23];
    const float* Wd2  = (const float*)d_in[24];
    const float* bd2  = (const float*)d_in[25];
    const float* Wd3  = (const float*)d_in[26];
    const float* bd3  = (const float*)d_in[27];
    float* out = (float*)d_out;

    float *p_gd;
    cudaGetSymbolAddress((void**)&p_gd, g_gd);
    __half *p_z, *p_fh, *p_zd, *p_zd2, *p_h1, *p_h2;
    cudaGetSymbolAddress((void**)&p_z,   g_z);
    cudaGetSymbolAddress((void**)&p_fh,  g_fh);
    cudaGetSymbolAddress((void**)&p_zd,  g_zd);
    cudaGetSymbolAddress((void**)&p_zd2, g_zd2);
    cudaGetSymbolAddress((void**)&p_h1,  g_h1);
    cudaGetSymbolAddress((void**)&p_h2,  g_h2);
    __half *wf1, *wf2, *wm, *wd1, *wd2;
    cudaGetSymbolAddress((void**)&wf1, g_wf1);
    cudaGetSymbolAddress((void**)&wf2, g_wf2);
    cudaGetSymbolAddress((void**)&wm,  g_wm);
    cudaGetSymbolAddress((void**)&wd1, g_wd1);
    cudaGetSymbolAddress((void**)&wd2, g_wd2);

    const int smem_t = (NC*9 + NE*9*HID + NE*HID + XD*HH + HH + XD*NE + NE)*4;
    const int smem_m = (NT*9 + NT + NT)*4;
    cudaFuncSetAttribute(target_kernel, cudaFuncAttributeMaxDynamicSharedMemorySize, smem_t);
    cudaFuncSetAttribute(moran_kernel,  cudaFuncAttributeMaxDynamicSharedMemorySize, smem_m);
    cudaFuncSetAttribute(mma_gemm,      cudaFuncAttributeMaxDynamicSharedMemorySize, SMEM_GEMM);

    PrepDesc pd0 = { Wf1, wf1, 512, 128, 512*128 };
    PrepDesc pd1 = { Wf2, wf2, 128, 256, 128*256 };
    PrepDesc pd2 = { Wed, wm,  384, 384, 4*384*384 };
    PrepDesc pd3 = { Wd1, wd1, 384, 256, 384*256 };
    PrepDesc pd4 = { Wd2, wd2, 256, 256, 256*256 };
    prep_all<<<dim3(160, 5), 256>>>(pd0, pd1, pd2, pd3, pd4);

    enc3_kernel<<<BSZ, 256>>>(cx, cy, Wp3, bp3, Wlin, blin);
    target_kernel<<<256, 256, smem_t>>>(cx, cy, txp, Wee, bee, Wge, bge, Wat, bat);
    // fps1: relu(z @ Wf1 + b)
    mma_gemm<<<dim3(256,2), 256, SMEM_GEMM>>>(p_z,   wf1, bf1, nullptr, p_fh,  512, 128, 0,   1, 1);
    // fps2: r = fh @ Wf2 + b -> zd[:,128:384]
    mma_gemm<<<dim3(256,4), 256, SMEM_GEMM>>>(p_fh,  wf2, bf2, nullptr, p_zd,  128, 384, 128, 1, 0);
    decgate_kernel<<<NTT/8, 256>>>(Wgd, bgd);
    // decoder MoE (gate-scaled A rows, accumulate over experts)
    mma_gemm<<<dim3(256,6), 256, SMEM_GEMM>>>(p_zd,  wm,  bed, p_gd,    p_zd2, 384, 384, 0,   4, 0);
    mma_gemm<<<dim3(256,4), 256, SMEM_GEMM>>>(p_zd2, wd1, bd1, nullptr, p_h1,  384, 256, 0,   1, 1);
    mma_gemm<<<dim3(256,4), 256, SMEM_GEMM>>>(p_h1,  wd2, bd2, nullptr, p_h2,  256, 256, 0,   1, 1);
    head_kernel<<<NTT/8, 256>>>(Wd3, bd3, out);
    moran_kernel<<<256, 256, smem_m>>>(txp, typ, out);
}

// round 14
// speedup vs baseline: 1.0263x; 1.0263x over previous
#include <cuda_runtime.h>
#include <cuda_fp16.h>
#include <cstdint>
#include <math.h>

#define BSZ 16
#define NC  1024
#define NT  2048
#define NTT (BSZ*NT)
#define XD  8
#define HID 256
#define HH  128
#define DD  384
#define NE  4

// ---------------- scratch ----------------
__device__ float g_enc3[BSZ*HID];
__device__ float g_gd [(size_t)NTT*NE];

// activations: single fp16
__device__ __half g_z  [(size_t)NTT*512];
__device__ __half g_fh [(size_t)NTT*HH];
__device__ __half g_zd [(size_t)NTT*DD];
__device__ __half g_zd2[(size_t)NTT*DD];
__device__ __half g_h1 [(size_t)NTT*HID];
__device__ __half g_h2 [(size_t)NTT*HID];

// weights: single fp16, pre-transposed to [N,K] K-major
__device__ __half g_wf1[128*512];
__device__ __half g_wf2[256*128];
__device__ __half g_wm [4*384*384];
__device__ __half g_wd1[256*384];
__device__ __half g_wd2[256*256];

// ---------------- weight prep: all 5 tensors in one launch ----------------
struct PrepDesc { const float* W; __half* O; int K; int N; int total; };

__global__ __launch_bounds__(256) void prep_all(
    PrepDesc d0, PrepDesc d1, PrepDesc d2, PrepDesc d3, PrepDesc d4)
{
    PrepDesc d;
    switch (blockIdx.y) {
        case 0: d = d0; break;
        case 1: d = d1; break;
        case 2: d = d2; break;
        case 3: d = d3; break;
        default: d = d4; break;
    }
    int KN = d.K * d.N;
    for (int idx = blockIdx.x*256 + threadIdx.x; idx < d.total; idx += gridDim.x*256) {
        int e = idx / KN, rem = idx - e*KN;
        int n = rem / d.K, k = rem - n*d.K;
        d.O[idx] = __float2half_rn(d.W[(size_t)e*KN + (size_t)k*d.N + n]);
    }
}

// ---------------- mma.sync helpers ----------------
__device__ __forceinline__ uint32_t smem_u32(const void* p) {
    uint32_t a;
    asm("{ .reg .u64 t; cvta.to.shared.u64 t, %1; cvt.u32.u64 %0, t; }" : "=r"(a) : "l"(p));
    return a;
}
__device__ __forceinline__ void ldm_x4(uint32_t* r, uint32_t addr) {
    asm volatile("ldmatrix.sync.aligned.m8n8.x4.shared.b16 {%0,%1,%2,%3}, [%4];"
        : "=r"(r[0]), "=r"(r[1]), "=r"(r[2]), "=r"(r[3]) : "r"(addr));
}
__device__ __forceinline__ void mma16816(float* d, const uint32_t* a, const uint32_t* b) {
    asm volatile(
        "mma.sync.aligned.m16n8k16.row.col.f32.f16.f16.f32 "
        "{%0,%1,%2,%3}, {%4,%5,%6,%7}, {%8,%9}, {%0,%1,%2,%3};"
        : "+f"(d[0]), "+f"(d[1]), "+f"(d[2]), "+f"(d[3])
        : "r"(a[0]), "r"(a[1]), "r"(a[2]), "r"(a[3]), "r"(b[0]), "r"(b[1]));
}
// L2-only bulk copy: keep L1 bandwidth for ldmatrix
__device__ __forceinline__ void cp16(uint32_t dst, const void* src) {
    asm volatile("cp.async.cg.shared.global [%0], [%1], 16;" :: "r"(dst), "l"(src));
}
__device__ __forceinline__ void cp_commit() { asm volatile("cp.async.commit_group;"); }
__device__ __forceinline__ void cp_wait0()  { asm volatile("cp.async.wait_group 0;"); }

// smem: fp16, BK=64, row stride 72 elems (144B; +4 banks/row -> ldmatrix conflict-free)
#define LDS   72
#define TILEB 18432            // 128*72*2 bytes
#define OFF_A(s) ((s)*TILEB)
#define OFF_B(s) ((2+(s))*TILEB)
#define SMEM_GEMM  73728

// C[M,Nfull](@ldc,coff) fp16 = act( rowscale(A) @ B^T + bias_eff )
// A fp16, B fp16 [N,K] expert-stacked; gate!=null: A rows scaled per expert
// (LDG+scale+STS path), acc over experts, gated bias. Non-gated: pure cp.async.
__global__ __launch_bounds__(256, 2) void mma_gemm(
    const __half* __restrict__ A, const __half* __restrict__ Bw,
    const float* __restrict__ bias, const float* __restrict__ gate,
    __half* __restrict__ C,
    int K, int ldc, int coff, int nexp, int relu)
{
    extern __shared__ char smc[];
    __shared__ float sbias[NE*128];
    uint32_t smb = smem_u32(smc);
    int tid = threadIdx.x;
    int lane = tid & 31, warp = tid >> 5;
    int wm = warp >> 2, wn = warp & 3;          // 2x4 warps: 64x32 warp tile
    int m0 = blockIdx.x * 128, n0 = blockIdx.y * 128;
    int Nfull = gridDim.y * 128;
    size_t bstride = (size_t)Nfull * K;

    for (int i = tid; i < nexp*128; i += 256)
        sbias[i] = bias[(size_t)(i >> 7) * Nfull + n0 + (i & 127)];

    float acc[4][4][4];
    #pragma unroll
    for (int mi = 0; mi < 4; mi++)
        #pragma unroll
        for (int ni = 0; ni < 4; ni++)
            #pragma unroll
            for (int q = 0; q < 4; q++) acc[mi][ni][q] = 0.f;

    const int tiles = K >> 6;                   // BK = 64
    const int T = nexp * tiles;

    // 16B chunk mapping: tile = 128 rows x 64 fp16 = 1024 chunks; 4 per thread
    int crow[4], ccol[4];
    #pragma unroll
    for (int i = 0; i < 4; i++) { int c = tid + i*256; crow[i] = c >> 3; ccol[i] = (c & 7) << 3; }

    uint4 ar[4]; float gv[4];

    auto load_async = [&](int s, int it2) {
        int e = it2 / tiles, k0 = (it2 - e*tiles) << 6;
        const __half* Bh = Bw + (size_t)e * bstride;
        #pragma unroll
        for (int i = 0; i < 4; i++) {
            uint32_t d = (uint32_t)(crow[i] * LDS + ccol[i]) * 2;
            cp16(smb + OFF_B(s) + d, &Bh[(size_t)(n0 + crow[i]) * K + k0 + ccol[i]]);
            if (!gate)
                cp16(smb + OFF_A(s) + d, &A[(size_t)(m0 + crow[i]) * K + k0 + ccol[i]]);
        }
        cp_commit();
    };
    auto load_a_regs = [&](int it2) {
        int e = it2 / tiles, k0 = (it2 - e*tiles) << 6;
        #pragma unroll
        for (int i = 0; i < 4; i++) {
            ar[i] = *(const uint4*)&A[(size_t)(m0 + crow[i]) * K + k0 + ccol[i]];
            gv[i] = gate[(size_t)(m0 + crow[i]) * 4 + e];
        }
    };
    auto store_a = [&](int s) {
        #pragma unroll
        for (int i = 0; i < 4; i++) {
            const uint32_t* pp = (const uint32_t*)&ar[i];
            uint32_t o[4];
            #pragma unroll
            for (int q = 0; q < 4; q++) {
                __half2 h2 = *(const __half2*)&pp[q];
                float2 f = __half22float2(h2);
                __half2 r = __floats2half2_rn(f.x * gv[i], f.y * gv[i]);
                o[q] = *(const uint32_t*)&r;
            }
            uint32_t d = (uint32_t)(crow[i] * LDS + ccol[i]) * 2;
            *(uint4*)(smc + OFF_A(s) + d) = make_uint4(o[0], o[1], o[2], o[3]);
        }
    };

    // prologue
    load_async(0, 0);
    if (gate) { load_a_regs(0); store_a(0); }
    cp_wait0();
    __syncthreads();

    for (int it = 0; it < T; it++) {
        int s = it & 1, ns = s ^ 1;
        if (it + 1 < T) {
            load_async(ns, it + 1);
            if (gate) load_a_regs(it + 1);
        }

        uint32_t aS = smb + OFF_A(s), bS = smb + OFF_B(s);
        #pragma unroll
        for (int ks = 0; ks < 4; ks++) {          // 4 x K16 within BK=64
            uint32_t bh[4][2], r4[4];
            #pragma unroll
            for (int np = 0; np < 2; np++) {
                uint32_t off = (uint32_t)((wn*32 + np*16 + (lane & 15)) * LDS
                                          + ks*16 + (lane >> 4)*8) * 2;
                ldm_x4(r4, bS + off);
                bh[np*2+0][0] = r4[0]; bh[np*2+0][1] = r4[2];
                bh[np*2+1][0] = r4[1]; bh[np*2+1][1] = r4[3];
            }
            uint32_t ah[4][4];
            #pragma unroll
            for (int mi = 0; mi < 4; mi++) {
                uint32_t off = (uint32_t)((wm*64 + mi*16 + (lane & 15)) * LDS
                                          + ks*16 + (lane >> 4)*8) * 2;
                ldm_x4(ah[mi], aS + off);
            }
            #pragma unroll
            for (int mi = 0; mi < 4; mi++)
                #pragma unroll
                for (int ni = 0; ni < 4; ni++)
                    mma16816(acc[mi][ni], ah[mi], bh[ni]);
        }
        if (it + 1 < T) {
            if (gate) store_a(ns);
            cp_wait0();
        }
        __syncthreads();
    }

    // epilogue: fp16 C, gated bias
    #pragma unroll
    for (int mi = 0; mi < 4; mi++) {
        #pragma unroll
        for (int sub = 0; sub < 2; sub++) {
            int row = m0 + wm*64 + mi*16 + (lane >> 2) + sub*8;
            float4 g4 = make_float4(0.f, 0.f, 0.f, 0.f);
            if (gate) g4 = *(const float4*)&gate[(size_t)row * 4];
            #pragma unroll
            for (int ni = 0; ni < 4; ni++) {
                int cl = wn*32 + ni*8 + (lane & 3)*2;
                float be0, be1;
                if (gate) {
                    be0 = g4.x*sbias[cl]     + g4.y*sbias[128+cl]
                        + g4.z*sbias[256+cl] + g4.w*sbias[384+cl];
                    be1 = g4.x*sbias[cl+1]     + g4.y*sbias[128+cl+1]
                        + g4.z*sbias[256+cl+1] + g4.w*sbias[384+cl+1];
                } else { be0 = sbias[cl]; be1 = sbias[cl+1]; }
                float v0 = acc[mi][ni][sub*2+0] + be0;
                float v1 = acc[mi][ni][sub*2+1] + be1;
                if (relu) { v0 = fmaxf(v0, 0.f); v1 = fmaxf(v1, 0.f); }
                *(__half2*)&C[(size_t)row * ldc + coff + n0 + cl] = __floats2half2_rn(v0, v1);
            }
        }
    }
}

// ---------------- enc3 ----------------
__global__ __launch_bounds__(256) void enc3_kernel(
    const float* __restrict__ cx, const float* __restrict__ cy,
    const float* __restrict__ Wp, const float* __restrict__ bp,
    const float* __restrict__ Wl, const float* __restrict__ bl)
{
    __shared__ float red[256*9];
    __shared__ float h0[HID];
    int b = blockIdx.x, tid = threadIdx.x;
    float l[9];
    #pragma unroll
    for (int x = 0; x < 9; x++) l[x] = 0.f;
    for (int c = tid; c < NC; c += 256) {
        #pragma unroll
        for (int x = 0; x < XD; x++) l[x] += cx[((size_t)b*NC + c)*XD + x];
        l[8] += cy[b*NC + c];
    }
    #pragma unroll
    for (int x = 0; x < 9; x++) red[tid*9 + x] = l[x];
    __syncthreads();
    for (int s = 128; s; s >>= 1) {
        if (tid < s) {
            #pragma unroll
            for (int x = 0; x < 9; x++) red[tid*9 + x] += red[(tid+s)*9 + x];
        }
        __syncthreads();
    }
    {
        int h = tid;
        float a = bp[h];
        #pragma unroll
        for (int x = 0; x < 9; x++) a = fmaf(red[x]*(1.f/NC), Wp[x*HID + h], a);
        h0[h] = a;
    }
    __syncthreads();
    {
        int h = tid;
        float a = bl[h];
        for (int k = 0; k < HID; k++) a = fmaf(h0[k], Wl[k*HID + h], a);
        g_enc3[b*HID + h] = a;
    }
}

// ---------------- per-target encoder (writes fp16 activations) ----------------
__global__ __launch_bounds__(256) void target_kernel(
    const float* __restrict__ cx, const float* __restrict__ cy,
    const float* __restrict__ txg,
    const float* __restrict__ Wee, const float* __restrict__ bee,
    const float* __restrict__ Wge, const float* __restrict__ bge,
    const float* __restrict__ Wat, const float* __restrict__ bat)
{
    extern __shared__ float smf[];
    float* sc  = smf;
    float* sWe = sc  + NC*9;
    float* sbe = sWe + NE*9*HID;
    float* sWa = sbe + NE*HID;
    float* sba = sWa + XD*HH;
    float* sWg = sba + HH;
    float* sbg = sWg + XD*NE;

    int b  = blockIdx.x >> 4;
    int t0 = (blockIdx.x & 15) << 7;
    int tid = threadIdx.x;

    for (int i = tid; i < NC*XD; i += 256) sc[(i>>3)*9 + (i&7)] = cx[(size_t)b*NC*XD + i];
    for (int i = tid; i < NC;    i += 256) sc[i*9 + 8] = cy[b*NC + i];
    for (int i = tid; i < NE*9*HID; i += 256) sWe[i] = Wee[i];
    for (int i = tid; i < NE*HID;   i += 256) sbe[i] = bee[i];
    for (int i = tid; i < XD*HH;    i += 256) sWa[i] = Wat[i];
    if (tid < HH)    sba[tid] = bat[tid];
    if (tid < XD*NE) sWg[tid] = Wge[tid];
    if (tid < NE)    sbg[tid] = bge[tid];
    __syncthreads();

    int warp = tid >> 5, lane = tid & 31;
    for (int tt = warp; tt < 128; tt += 8) {
        int t = t0 + tt;
        size_t gt = (size_t)b*NT + t;
        float tx[XD];
        #pragma unroll
        for (int x = 0; x < XD; x++) tx[x] = txg[gt*XD + x];

        float acc[10];
        #pragma unroll
        for (int i = 0; i < 10; i++) acc[i] = 0.f;
        for (int c = lane; c < NC; c += 32) {
            const float* p = &sc[c*9];
            float d2 = 1e-12f;
            #pragma unroll
            for (int x = 0; x < XD; x++) { float d = tx[x]-p[x]; d2 = fmaf(d, d, d2); }
            float dist = d2 * __frsqrt_rn(d2);
            float w = __expf(-dist);
            acc[9] += w;
            #pragma unroll
            for (int x = 0; x < 9; x++) acc[x] = fmaf(w, p[x], acc[x]);
        }
        #pragma unroll
        for (int o = 16; o; o >>= 1) {
            #pragma unroll
            for (int i = 0; i < 10; i++) acc[i] += __shfl_xor_sync(0xffffffffu, acc[i], o);
        }
        float inv = 1.f/acc[9];
        float s[9];
        #pragma unroll
        for (int x = 0; x < 9; x++) s[x] = acc[x]*inv;

        float g[NE];
        #pragma unroll
        for (int e = 0; e < NE; e++) {
            float a = sbg[e];
            #pragma unroll
            for (int x = 0; x < XD; x++) a = fmaf(tx[x], sWg[x*NE + e], a);
            g[e] = a;
        }
        float gm = fmaxf(fmaxf(g[0],g[1]), fmaxf(g[2],g[3]));
        float gs = 0.f;
        #pragma unroll
        for (int e = 0; e < NE; e++) { g[e] = __expf(g[e]-gm); gs += g[e]; }
        float gi = 1.f/gs;
        #pragma unroll
        for (int e = 0; e < NE; e++) g[e] *= gi;

        #pragma unroll
        for (int j = 0; j < 8; j++) {
            int h = lane + 32*j;
            float o2 = 0.f;
            #pragma unroll
            for (int e = 0; e < NE; e++) {
                float a = sbe[e*HID + h];
                #pragma unroll
                for (int x = 0; x < 9; x++) a = fmaf(s[x], sWe[(e*9 + x)*HID + h], a);
                o2 = fmaf(g[e], a, o2);
            }
            g_z[gt*512 + 256 + h] = __float2half_rn(o2);
            g_z[gt*512 + h] = __float2half_rn(g_enc3[b*HID + h]);
        }
        #pragma unroll
        for (int j = 0; j < 4; j++) {
            int h = lane + 32*j;
            float a = sba[h];
            #pragma unroll
            for (int x = 0; x < XD; x++) a = fmaf(tx[x], sWa[x*HH + h], a);
            g_zd[gt*DD + h] = __float2half_rn(a);
        }
    }
}

// ---------------- decoder gate ----------------
__global__ __launch_bounds__(256) void decgate_kernel(
    const float* __restrict__ Wg, const float* __restrict__ bg)
{
    int warp = threadIdx.x >> 5, lane = threadIdx.x & 31;
    size_t gt = (size_t)blockIdx.x*8 + warp;
    float a0=0.f, a1=0.f, a2=0.f, a3=0.f;
    const float4* W4 = (const float4*)Wg;
    for (int k = lane; k < DD; k += 32) {
        float z = __half2float(g_zd[gt*DD + k]);
        float4 w = W4[k];
        a0 = fmaf(z, w.x, a0); a1 = fmaf(z, w.y, a1);
        a2 = fmaf(z, w.z, a2); a3 = fmaf(z, w.w, a3);
    }
    #pragma unroll
    for (int o = 16; o; o >>= 1) {
        a0 += __shfl_xor_sync(0xffffffffu, a0, o);
        a1 += __shfl_xor_sync(0xffffffffu, a1, o);
        a2 += __shfl_xor_sync(0xffffffffu, a2, o);
        a3 += __shfl_xor_sync(0xffffffffu, a3, o);
    }
    a0 += bg[0]; a1 += bg[1]; a2 += bg[2]; a3 += bg[3];
    float m = fmaxf(fmaxf(a0,a1), fmaxf(a2,a3));
    float e0 = __expf(a0-m), e1 = __expf(a1-m), e2 = __expf(a2-m), e3 = __expf(a3-m);
    float inv = 1.f/(e0+e1+e2+e3);
    if (lane == 0) {
        g_gd[gt*4+0] = e0*inv; g_gd[gt*4+1] = e1*inv;
        g_gd[gt*4+2] = e2*inv; g_gd[gt*4+3] = e3*inv;
    }
}

// ---------------- head ----------------
__global__ __launch_bounds__(256) void head_kernel(
    const float* __restrict__ W3, const float* __restrict__ b3, float* __restrict__ out)
{
    int warp = threadIdx.x >> 5, lane = threadIdx.x & 31;
    size_t gt = (size_t)blockIdx.x*8 + warp;
    float a0=0.f, a1=0.f;
    const float2* W2 = (const float2*)W3;
    for (int k = lane; k < HID; k += 32) {
        float h = __half2float(g_h2[gt*HID + k]);
        float2 w = W2[k];
        a0 = fmaf(h, w.x, a0); a1 = fmaf(h, w.y, a1);
    }
    #pragma unroll
    for (int o = 16; o; o >>= 1) {
        a0 += __shfl_xor_sync(0xffffffffu, a0, o);
        a1 += __shfl_xor_sync(0xffffffffu, a1, o);
    }
    if (lane == 0) {
        float mu = a0 + b3[0];
        float x  = a1 + b3[1];
        float sp = fmaxf(x, 0.f) + log1pf(__expf(-fabsf(x)));
        out[gt]       = mu;
        out[NTT + gt] = 0.1f + 0.9f*sp;
    }
}

// ---------------- Moran k-NN lag ----------------
__global__ __launch_bounds__(256) void moran_kernel(
    const float* __restrict__ txg, const float* __restrict__ tyg, float* __restrict__ out)
{
    extern __shared__ float smf[];
    float* st  = smf;
    float* sy  = st + NT*9;
    float* smu = sy + NT;
    int b  = blockIdx.x >> 4;
    int t0 = (blockIdx.x & 15) << 7;
    int tid = threadIdx.x;

    for (int i = tid; i < NT*XD; i += 256) st[(i>>3)*9 + (i&7)] = txg[(size_t)b*NT*XD + i];
    for (int i = tid; i < NT; i += 256) { sy[i] = tyg[b*NT + i]; smu[i] = out[b*NT + i]; }
    __syncthreads();
    for (int i = tid; i < NT; i += 256) {
        float n = 0.f;
        #pragma unroll
        for (int x = 0; x < XD; x++) { float v = st[i*9 + x]; n = fmaf(v, v, n); }
        st[i*9 + 8] = n;
    }
    __syncthreads();

    int warp = tid >> 5, lane = tid & 31;
    for (int tt = warp; tt < 128; tt += 8) {
        int t = t0 + tt;
        float tx[XD];
        #pragma unroll
        for (int x = 0; x < XD; x++) tx[x] = st[t*9 + x];
        float tn = st[t*9 + 8];

        float bd0=INFINITY,bd1=INFINITY,bd2=INFINITY,bd3=INFINITY,bd4=INFINITY;
        int   bi0=0,bi1=0,bi2=0,bi3=0,bi4=0;
        for (int c = lane; c < NT; c += 32) {
            if (c == t) continue;
            const float* p = &st[c*9];
            float dot = 0.f;
            #pragma unroll
            for (int x = 0; x < XD; x++) dot = fmaf(tx[x], p[x], dot);
            float d2 = tn + p[8] - 2.f*dot;
            d2 = fmaxf(d2, 0.f) + 1e-12f;
            if (d2 < bd4) {
                bd4 = d2; bi4 = c;
                if (bd4 < bd3) { float td=bd3; bd3=bd4; bd4=td; int ti=bi3; bi3=bi4; bi4=ti; }
                if (bd3 < bd2) { float td=bd2; bd2=bd3; bd3=td; int ti=bi2; bi2=bi3; bi3=ti; }
                if (bd2 < bd1) { float td=bd1; bd1=bd2; bd2=td; int ti=bi1; bi1=bi2; bi2=ti; }
                if (bd1 < bd0) { float td=bd0; bd0=bd1; bd1=td; int ti=bi0; bi0=bi1; bi1=ti; }
            }
        }
        float seld[5]; int seli[5];
        #pragma unroll
        for (int r = 0; r < 5; r++) {
            float rd = bd0; int ri = bi0; int rl = lane;
            #pragma unroll
            for (int o = 16; o; o >>= 1) {
                float od = __shfl_xor_sync(0xffffffffu, rd, o);
                int   oi = __shfl_xor_sync(0xffffffffu, ri, o);
                int   ol = __shfl_xor_sync(0xffffffffu, rl, o);
                if (od < rd || (od == rd && oi < ri)) { rd = od; ri = oi; rl = ol; }
            }
            seld[r] = rd; seli[r] = ri;
            if (lane == rl) {
                bd0=bd1; bi0=bi1; bd1=bd2; bi1=bi2; bd2=bd3; bi2=bi3;
                bd3=bd4; bi3=bi4; bd4=INFINITY; bi4=0x7fffffff;
            }
        }
        if (lane == 0) {
            float w[5], ws = 0.f;
            #pragma unroll
            for (int r = 0; r < 5; r++) { w[r] = __expf(-0.1f*sqrtf(seld[r])); ws += w[r]; }
            float inv = 1.f/ws;
            float ly = 0.f, lm = 0.f;
            #pragma unroll
            for (int r = 0; r < 5; r++) {
                float wr = w[r]*inv;
                ly = fmaf(wr, sy[seli[r]],  ly);
                lm = fmaf(wr, smu[seli[r]], lm);
            }
            size_t gt = (size_t)b*NT + t;
            out[2*(size_t)NTT + gt] = ly;
            out[3*(size_t)NTT + gt] = lm;
        }
    }
}

// ---------------- launch ----------------
extern "C" void kernel_launch(void* const* d_in, const int* in_sizes, int n_in,
                              void* d_out, int out_size)
{
    const float* cx   = (const float*)d_in[0];
    const float* cy   = (const float*)d_in[1];
    const float* txp  = (const float*)d_in[2];
    const float* typ  = (const float*)d_in[3];
    const float* Wge  = (const float*)d_in[4];
    const float* bge  = (const float*)d_in[5];
    const float* Wee  = (const float*)d_in[6];
    const float* bee  = (const float*)d_in[7];
    const float* Wp3  = (const float*)d_in[8];
    const float* bp3  = (const float*)d_in[9];
    const float* Wlin = (const float*)d_in[10];
    const float* blin = (const float*)d_in[11];
    const float* Wf1  = (const float*)d_in[12];
    const float* bf1  = (const float*)d_in[13];
    const float* Wf2  = (const float*)d_in[14];
    const float* bf2  = (const float*)d_in[15];
    const float* Wat  = (const float*)d_in[16];
    const float* bat  = (const float*)d_in[17];
    const float* Wgd  = (const float*)d_in[18];
    const float* bgd  = (const float*)d_in[19];
    const float* Wed  = (const float*)d_in[20];
    const float* bed  = (const float*)d_in[21];
    const float* Wd1  = (const float*)d_in[22];
    const float* bd1  = (const float*)d_in[23];
    const float* Wd2  = (const float*)d_in[24];
    const float* bd2  = (const float*)d_in[25];
    const float* Wd3  = (const float*)d_in[26];
    const float* bd3  = (const float*)d_in[27];
    float* out = (float*)d_out;

    float *p_gd;
    cudaGetSymbolAddress((void**)&p_gd, g_gd);
    __half *p_z, *p_fh, *p_zd, *p_zd2, *p_h1, *p_h2;
    cudaGetSymbolAddress((void**)&p_z,   g_z);
    cudaGetSymbolAddress((void**)&p_fh,  g_fh);
    cudaGetSymbolAddress((void**)&p_zd,  g_zd);
    cudaGetSymbolAddress((void**)&p_zd2, g_zd2);
    cudaGetSymbolAddress((void**)&p_h1,  g_h1);
    cudaGetSymbolAddress((void**)&p_h2,  g_h2);
    __half *wf1, *wf2, *wm, *wd1, *wd2;
    cudaGetSymbolAddress((void**)&wf1, g_wf1);
    cudaGetSymbolAddress((void**)&wf2, g_wf2);
    cudaGetSymbolAddress((void**)&wm,  g_wm);
    cudaGetSymbolAddress((void**)&wd1, g_wd1);
    cudaGetSymbolAddress((void**)&wd2, g_wd2);

    const int smem_t = (NC*9 + NE*9*HID + NE*HID + XD*HH + HH + XD*NE + NE)*4;
    const int smem_m = (NT*9 + NT + NT)*4;
    cudaFuncSetAttribute(target_kernel, cudaFuncAttributeMaxDynamicSharedMemorySize, smem_t);
    cudaFuncSetAttribute(moran_kernel,  cudaFuncAttributeMaxDynamicSharedMemorySize, smem_m);
    cudaFuncSetAttribute(mma_gemm,      cudaFuncAttributeMaxDynamicSharedMemorySize, SMEM_GEMM);

    PrepDesc pd0 = { Wf1, wf1, 512, 128, 512*128 };
    PrepDesc pd1 = { Wf2, wf2, 128, 256, 128*256 };
    PrepDesc pd2 = { Wed, wm,  384, 384, 4*384*384 };
    PrepDesc pd3 = { Wd1, wd1, 384, 256, 384*256 };
    PrepDesc pd4 = { Wd2, wd2, 256, 256, 256*256 };
    prep_all<<<dim3(160, 5), 256>>>(pd0, pd1, pd2, pd3, pd4);

    enc3_kernel<<<BSZ, 256>>>(cx, cy, Wp3, bp3, Wlin, blin);
    target_kernel<<<256, 256, smem_t>>>(cx, cy, txp, Wee, bee, Wge, bge, Wat, bat);
    // fps1: relu(z @ Wf1 + b)
    mma_gemm<<<dim3(256,1), 256, SMEM_GEMM>>>(p_z,   wf1, bf1, nullptr, p_fh,  512, 128, 0,   1, 1);
    // fps2: r = fh @ Wf2 + b -> zd[:,128:384]
    mma_gemm<<<dim3(256,2), 256, SMEM_GEMM>>>(p_fh,  wf2, bf2, nullptr, p_zd,  128, 384, 128, 1, 0);
    decgate_kernel<<<NTT/8, 256>>>(Wgd, bgd);
    // decoder MoE (gate-scaled A rows, accumulate over experts)
    mma_gemm<<<dim3(256,3), 256, SMEM_GEMM>>>(p_zd,  wm,  bed, p_gd,    p_zd2, 384, 384, 0,   4, 0);
    mma_gemm<<<dim3(256,2), 256, SMEM_GEMM>>>(p_zd2, wd1, bd1, nullptr, p_h1,  384, 256, 0,   1, 1);
    mma_gemm<<<dim3(256,2), 256, SMEM_GEMM>>>(p_h1,  wd2, bd2, nullptr, p_h2,  256, 256, 0,   1, 1);
    head_kernel<<<NTT/8, 256>>>(Wd3, bd3, out);
    moran_kernel<<<256, 256, smem_m>>>(txp, typ, out);
}

// round 15
// speedup vs baseline: 1.0345x; 1.0080x over previous
#include <cuda_runtime.h>
#include <cuda_fp16.h>
#include <cstdint>
#include <math.h>

#define BSZ 16
#define NC  1024
#define NT  2048
#define NTT (BSZ*NT)
#define XD  8
#define HID 256
#define HH  128
#define DD  384
#define NE  4

// ---------------- scratch ----------------
__device__ float g_enc3[BSZ*HID];
__device__ float g_gd [(size_t)NTT*NE];

// activations: single fp16
__device__ __half g_z  [(size_t)NTT*512];
__device__ __half g_fh [(size_t)NTT*HH];
__device__ __half g_zd [(size_t)NTT*DD];
__device__ __half g_zd2[(size_t)NTT*DD];
__device__ __half g_h1 [(size_t)NTT*HID];
__device__ __half g_h2 [(size_t)NTT*HID];

// weights: single fp16, pre-transposed to [N,K] K-major
__device__ __half g_wf1[128*512];
__device__ __half g_wf2[256*128];
__device__ __half g_wm [4*384*384];
__device__ __half g_wd1[256*384];
__device__ __half g_wd2[256*256];

// ---------------- weight prep: all 5 tensors in one launch ----------------
struct PrepDesc { const float* W; __half* O; int K; int N; int total; };

__global__ __launch_bounds__(256) void prep_all(
    PrepDesc d0, PrepDesc d1, PrepDesc d2, PrepDesc d3, PrepDesc d4)
{
    PrepDesc d;
    switch (blockIdx.y) {
        case 0: d = d0; break;
        case 1: d = d1; break;
        case 2: d = d2; break;
        case 3: d = d3; break;
        default: d = d4; break;
    }
    int KN = d.K * d.N;
    for (int idx = blockIdx.x*256 + threadIdx.x; idx < d.total; idx += gridDim.x*256) {
        int e = idx / KN, rem = idx - e*KN;
        int n = rem / d.K, k = rem - n*d.K;
        d.O[idx] = __float2half_rn(d.W[(size_t)e*KN + (size_t)k*d.N + n]);
    }
}

// ---------------- mma.sync helpers ----------------
__device__ __forceinline__ uint32_t smem_u32(const void* p) {
    uint32_t a;
    asm("{ .reg .u64 t; cvta.to.shared.u64 t, %1; cvt.u32.u64 %0, t; }" : "=r"(a) : "l"(p));
    return a;
}
__device__ __forceinline__ void ldm_x4(uint32_t* r, uint32_t addr) {
    asm volatile("ldmatrix.sync.aligned.m8n8.x4.shared.b16 {%0,%1,%2,%3}, [%4];"
        : "=r"(r[0]), "=r"(r[1]), "=r"(r[2]), "=r"(r[3]) : "r"(addr));
}
__device__ __forceinline__ void mma16816(float* d, const uint32_t* a, const uint32_t* b) {
    asm volatile(
        "mma.sync.aligned.m16n8k16.row.col.f32.f16.f16.f32 "
        "{%0,%1,%2,%3}, {%4,%5,%6,%7}, {%8,%9}, {%0,%1,%2,%3};"
        : "+f"(d[0]), "+f"(d[1]), "+f"(d[2]), "+f"(d[3])
        : "r"(a[0]), "r"(a[1]), "r"(a[2]), "r"(a[3]), "r"(b[0]), "r"(b[1]));
}
__device__ __forceinline__ void cp16(uint32_t dst, const void* src) {
    asm volatile("cp.async.ca.shared.global [%0], [%1], 16;" :: "r"(dst), "l"(src));
}
__device__ __forceinline__ void cp_commit() { asm volatile("cp.async.commit_group;"); }
__device__ __forceinline__ void cp_wait0()  { asm volatile("cp.async.wait_group 0;"); }

// smem: fp16, BK=64, row stride 72 elems (144B; +4 banks/row -> ldmatrix conflict-free)
#define LDS   72
#define TILEB 18432            // 128*72*2 bytes
#define OFF_A(s) ((s)*TILEB)
#define OFF_B(s) ((2+(s))*TILEB)
#define SMEM_GEMM  73728

// C[M,Nfull](@ldc,coff) fp16 = act( rowscale(A) @ B^T + bias_eff )
// A fp16, B fp16 [N,K] expert-stacked; gate!=null: A rows scaled per expert
// (LDG+scale+STS path), acc over experts, gated bias. Non-gated: pure cp.async.
__global__ __launch_bounds__(256, 2) void mma_gemm(
    const __half* __restrict__ A, const __half* __restrict__ Bw,
    const float* __restrict__ bias, const float* __restrict__ gate,
    __half* __restrict__ C,
    int K, int ldc, int coff, int nexp, int relu)
{
    extern __shared__ char smc[];
    __shared__ float sbias[NE*128];
    uint32_t smb = smem_u32(smc);
    int tid = threadIdx.x;
    int lane = tid & 31, warp = tid >> 5;
    int wm = warp >> 2, wn = warp & 3;          // 2x4 warps: 64x32 warp tile
    int m0 = blockIdx.x * 128, n0 = blockIdx.y * 128;
    int Nfull = gridDim.y * 128;
    size_t bstride = (size_t)Nfull * K;

    for (int i = tid; i < nexp*128; i += 256)
        sbias[i] = bias[(size_t)(i >> 7) * Nfull + n0 + (i & 127)];

    float acc[4][4][4];
    #pragma unroll
    for (int mi = 0; mi < 4; mi++)
        #pragma unroll
        for (int ni = 0; ni < 4; ni++)
            #pragma unroll
            for (int q = 0; q < 4; q++) acc[mi][ni][q] = 0.f;

    const int tiles = K >> 6;                   // BK = 64
    const int T = nexp * tiles;

    // 16B chunk mapping: tile = 128 rows x 64 fp16 = 1024 chunks; 4 per thread
    int crow[4], ccol[4];
    #pragma unroll
    for (int i = 0; i < 4; i++) { int c = tid + i*256; crow[i] = c >> 3; ccol[i] = (c & 7) << 3; }

    uint4 ar[4]; float gv[4];

    auto load_async = [&](int s, int it2) {
        int e = it2 / tiles, k0 = (it2 - e*tiles) << 6;
        const __half* Bh = Bw + (size_t)e * bstride;
        #pragma unroll
        for (int i = 0; i < 4; i++) {
            uint32_t d = (uint32_t)(crow[i] * LDS + ccol[i]) * 2;
            cp16(smb + OFF_B(s) + d, &Bh[(size_t)(n0 + crow[i]) * K + k0 + ccol[i]]);
            if (!gate)
                cp16(smb + OFF_A(s) + d, &A[(size_t)(m0 + crow[i]) * K + k0 + ccol[i]]);
        }
        cp_commit();
    };
    auto load_a_regs = [&](int it2) {
        int e = it2 / tiles, k0 = (it2 - e*tiles) << 6;
        #pragma unroll
        for (int i = 0; i < 4; i++) {
            ar[i] = *(const uint4*)&A[(size_t)(m0 + crow[i]) * K + k0 + ccol[i]];
            gv[i] = gate[(size_t)(m0 + crow[i]) * 4 + e];
        }
    };
    auto store_a = [&](int s) {
        #pragma unroll
        for (int i = 0; i < 4; i++) {
            const uint32_t* pp = (const uint32_t*)&ar[i];
            uint32_t o[4];
            #pragma unroll
            for (int q = 0; q < 4; q++) {
                __half2 h2 = *(const __half2*)&pp[q];
                float2 f = __half22float2(h2);
                __half2 r = __floats2half2_rn(f.x * gv[i], f.y * gv[i]);
                o[q] = *(const uint32_t*)&r;
            }
            uint32_t d = (uint32_t)(crow[i] * LDS + ccol[i]) * 2;
            *(uint4*)(smc + OFF_A(s) + d) = make_uint4(o[0], o[1], o[2], o[3]);
        }
    };

    // prologue
    load_async(0, 0);
    if (gate) { load_a_regs(0); store_a(0); }
    cp_wait0();
    __syncthreads();

    for (int it = 0; it < T; it++) {
        int s = it & 1, ns = s ^ 1;
        if (it + 1 < T) {
            load_async(ns, it + 1);
            if (gate) load_a_regs(it + 1);
        }

        uint32_t aS = smb + OFF_A(s), bS = smb + OFF_B(s);
        #pragma unroll
        for (int ks = 0; ks < 4; ks++) {          // 4 x K16 within BK=64
            uint32_t bh[4][2], r4[4];
            #pragma unroll
            for (int np = 0; np < 2; np++) {
                uint32_t off = (uint32_t)((wn*32 + np*16 + (lane & 15)) * LDS
                                          + ks*16 + (lane >> 4)*8) * 2;
                ldm_x4(r4, bS + off);
                bh[np*2+0][0] = r4[0]; bh[np*2+0][1] = r4[2];
                bh[np*2+1][0] = r4[1]; bh[np*2+1][1] = r4[3];
            }
            uint32_t ah[4][4];
            #pragma unroll
            for (int mi = 0; mi < 4; mi++) {
                uint32_t off = (uint32_t)((wm*64 + mi*16 + (lane & 15)) * LDS
                                          + ks*16 + (lane >> 4)*8) * 2;
                ldm_x4(ah[mi], aS + off);
            }
            #pragma unroll
            for (int mi = 0; mi < 4; mi++)
                #pragma unroll
                for (int ni = 0; ni < 4; ni++)
                    mma16816(acc[mi][ni], ah[mi], bh[ni]);
        }
        if (it + 1 < T) {
            if (gate) store_a(ns);
            cp_wait0();
        }
        __syncthreads();
    }

    // epilogue: fp16 C, gated bias
    #pragma unroll
    for (int mi = 0; mi < 4; mi++) {
        #pragma unroll
        for (int sub = 0; sub < 2; sub++) {
            int row = m0 + wm*64 + mi*16 + (lane >> 2) + sub*8;
            float4 g4 = make_float4(0.f, 0.f, 0.f, 0.f);
            if (gate) g4 = *(const float4*)&gate[(size_t)row * 4];
            #pragma unroll
            for (int ni = 0; ni < 4; ni++) {
                int cl = wn*32 + ni*8 + (lane & 3)*2;
                float be0, be1;
                if (gate) {
                    be0 = g4.x*sbias[cl]     + g4.y*sbias[128+cl]
                        + g4.z*sbias[256+cl] + g4.w*sbias[384+cl];
                    be1 = g4.x*sbias[cl+1]     + g4.y*sbias[128+cl+1]
                        + g4.z*sbias[256+cl+1] + g4.w*sbias[384+cl+1];
                } else { be0 = sbias[cl]; be1 = sbias[cl+1]; }
                float v0 = acc[mi][ni][sub*2+0] + be0;
                float v1 = acc[mi][ni][sub*2+1] + be1;
                if (relu) { v0 = fmaxf(v0, 0.f); v1 = fmaxf(v1, 0.f); }
                *(__half2*)&C[(size_t)row * ldc + coff + n0 + cl] = __floats2half2_rn(v0, v1);
            }
        }
    }
}

// ---------------- enc3 ----------------
__global__ __launch_bounds__(256) void enc3_kernel(
    const float* __restrict__ cx, const float* __restrict__ cy,
    const float* __restrict__ Wp, const float* __restrict__ bp,
    const float* __restrict__ Wl, const float* __restrict__ bl)
{
    __shared__ float red[256*9];
    __shared__ float h0[HID];
    int b = blockIdx.x, tid = threadIdx.x;
    float l[9];
    #pragma unroll
    for (int x = 0; x < 9; x++) l[x] = 0.f;
    for (int c = tid; c < NC; c += 256) {
        #pragma unroll
        for (int x = 0; x < XD; x++) l[x] += cx[((size_t)b*NC + c)*XD + x];
        l[8] += cy[b*NC + c];
    }
    #pragma unroll
    for (int x = 0; x < 9; x++) red[tid*9 + x] = l[x];
    __syncthreads();
    for (int s = 128; s; s >>= 1) {
        if (tid < s) {
            #pragma unroll
            for (int x = 0; x < 9; x++) red[tid*9 + x] += red[(tid+s)*9 + x];
        }
        __syncthreads();
    }
    {
        int h = tid;
        float a = bp[h];
        #pragma unroll
        for (int x = 0; x < 9; x++) a = fmaf(red[x]*(1.f/NC), Wp[x*HID + h], a);
        h0[h] = a;
    }
    __syncthreads();
    {
        int h = tid;
        float a = bl[h];
        for (int k = 0; k < HID; k++) a = fmaf(h0[k], Wl[k*HID + h], a);
        g_enc3[b*HID + h] = a;
    }
}

// ---------------- per-target encoder (writes fp16 activations) ----------------
__global__ __launch_bounds__(256) void target_kernel(
    const float* __restrict__ cx, const float* __restrict__ cy,
    const float* __restrict__ txg,
    const float* __restrict__ Wee, const float* __restrict__ bee,
    const float* __restrict__ Wge, const float* __restrict__ bge,
    const float* __restrict__ Wat, const float* __restrict__ bat)
{
    extern __shared__ float smf[];
    float* sc  = smf;
    float* sWe = sc  + NC*9;
    float* sbe = sWe + NE*9*HID;
    float* sWa = sbe + NE*HID;
    float* sba = sWa + XD*HH;
    float* sWg = sba + HH;
    float* sbg = sWg + XD*NE;

    int b  = blockIdx.x >> 4;
    int t0 = (blockIdx.x & 15) << 7;
    int tid = threadIdx.x;

    for (int i = tid; i < NC*XD; i += 256) sc[(i>>3)*9 + (i&7)] = cx[(size_t)b*NC*XD + i];
    for (int i = tid; i < NC;    i += 256) sc[i*9 + 8] = cy[b*NC + i];
    for (int i = tid; i < NE*9*HID; i += 256) sWe[i] = Wee[i];
    for (int i = tid; i < NE*HID;   i += 256) sbe[i] = bee[i];
    for (int i = tid; i < XD*HH;    i += 256) sWa[i] = Wat[i];
    if (tid < HH)    sba[tid] = bat[tid];
    if (tid < XD*NE) sWg[tid] = Wge[tid];
    if (tid < NE)    sbg[tid] = bge[tid];
    __syncthreads();

    int warp = tid >> 5, lane = tid & 31;
    for (int tt = warp; tt < 128; tt += 8) {
        int t = t0 + tt;
        size_t gt = (size_t)b*NT + t;
        float tx[XD];
        #pragma unroll
        for (int x = 0; x < XD; x++) tx[x] = txg[gt*XD + x];

        float acc[10];
        #pragma unroll
        for (int i = 0; i < 10; i++) acc[i] = 0.f;
        for (int c = lane; c < NC; c += 32) {
            const float* p = &sc[c*9];
            float d2 = 1e-12f;
            #pragma unroll
            for (int x = 0; x < XD; x++) { float d = tx[x]-p[x]; d2 = fmaf(d, d, d2); }
            float dist = d2 * __frsqrt_rn(d2);
            float w = __expf(-dist);
            acc[9] += w;
            #pragma unroll
            for (int x = 0; x < 9; x++) acc[x] = fmaf(w, p[x], acc[x]);
        }
        #pragma unroll
        for (int o = 16; o; o >>= 1) {
            #pragma unroll
            for (int i = 0; i < 10; i++) acc[i] += __shfl_xor_sync(0xffffffffu, acc[i], o);
        }
        float inv = 1.f/acc[9];
        float s[9];
        #pragma unroll
        for (int x = 0; x < 9; x++) s[x] = acc[x]*inv;

        float g[NE];
        #pragma unroll
        for (int e = 0; e < NE; e++) {
            float a = sbg[e];
            #pragma unroll
            for (int x = 0; x < XD; x++) a = fmaf(tx[x], sWg[x*NE + e], a);
            g[e] = a;
        }
        float gm = fmaxf(fmaxf(g[0],g[1]), fmaxf(g[2],g[3]));
        float gs = 0.f;
        #pragma unroll
        for (int e = 0; e < NE; e++) { g[e] = __expf(g[e]-gm); gs += g[e]; }
        float gi = 1.f/gs;
        #pragma unroll
        for (int e = 0; e < NE; e++) g[e] *= gi;

        #pragma unroll
        for (int j = 0; j < 8; j++) {
            int h = lane + 32*j;
            float o2 = 0.f;
            #pragma unroll
            for (int e = 0; e < NE; e++) {
                float a = sbe[e*HID + h];
                #pragma unroll
                for (int x = 0; x < 9; x++) a = fmaf(s[x], sWe[(e*9 + x)*HID + h], a);
                o2 = fmaf(g[e], a, o2);
            }
            g_z[gt*512 + 256 + h] = __float2half_rn(o2);
            g_z[gt*512 + h] = __float2half_rn(g_enc3[b*HID + h]);
        }
        #pragma unroll
        for (int j = 0; j < 4; j++) {
            int h = lane + 32*j;
            float a = sba[h];
            #pragma unroll
            for (int x = 0; x < XD; x++) a = fmaf(tx[x], sWa[x*HH + h], a);
            g_zd[gt*DD + h] = __float2half_rn(a);
        }
    }
}

// ---------------- decoder gate ----------------
__global__ __launch_bounds__(256) void decgate_kernel(
    const float* __restrict__ Wg, const float* __restrict__ bg)
{
    int warp = threadIdx.x >> 5, lane = threadIdx.x & 31;
    size_t gt = (size_t)blockIdx.x*8 + warp;
    float a0=0.f, a1=0.f, a2=0.f, a3=0.f;
    const float4* W4 = (const float4*)Wg;
    for (int k = lane; k < DD; k += 32) {
        float z = __half2float(g_zd[gt*DD + k]);
        float4 w = W4[k];
        a0 = fmaf(z, w.x, a0); a1 = fmaf(z, w.y, a1);
        a2 = fmaf(z, w.z, a2); a3 = fmaf(z, w.w, a3);
    }
    #pragma unroll
    for (int o = 16; o; o >>= 1) {
        a0 += __shfl_xor_sync(0xffffffffu, a0, o);
        a1 += __shfl_xor_sync(0xffffffffu, a1, o);
        a2 += __shfl_xor_sync(0xffffffffu, a2, o);
        a3 += __shfl_xor_sync(0xffffffffu, a3, o);
    }
    a0 += bg[0]; a1 += bg[1]; a2 += bg[2]; a3 += bg[3];
    float m = fmaxf(fmaxf(a0,a1), fmaxf(a2,a3));
    float e0 = __expf(a0-m), e1 = __expf(a1-m), e2 = __expf(a2-m), e3 = __expf(a3-m);
    float inv = 1.f/(e0+e1+e2+e3);
    if (lane == 0) {
        g_gd[gt*4+0] = e0*inv; g_gd[gt*4+1] = e1*inv;
        g_gd[gt*4+2] = e2*inv; g_gd[gt*4+3] = e3*inv;
    }
}

// ---------------- head ----------------
__global__ __launch_bounds__(256) void head_kernel(
    const float* __restrict__ W3, const float* __restrict__ b3, float* __restrict__ out)
{
    int warp = threadIdx.x >> 5, lane = threadIdx.x & 31;
    size_t gt = (size_t)blockIdx.x*8 + warp;
    float a0=0.f, a1=0.f;
    const float2* W2 = (const float2*)W3;
    for (int k = lane; k < HID; k += 32) {
        float h = __half2float(g_h2[gt*HID + k]);
        float2 w = W2[k];
        a0 = fmaf(h, w.x, a0); a1 = fmaf(h, w.y, a1);
    }
    #pragma unroll
    for (int o = 16; o; o >>= 1) {
        a0 += __shfl_xor_sync(0xffffffffu, a0, o);
        a1 += __shfl_xor_sync(0xffffffffu, a1, o);
    }
    if (lane == 0) {
        float mu = a0 + b3[0];
        float x  = a1 + b3[1];
        float sp = fmaxf(x, 0.f) + log1pf(__expf(-fabsf(x)));
        out[gt]       = mu;
        out[NTT + gt] = 0.1f + 0.9f*sp;
    }
}

// ---------------- Moran k-NN lag ----------------
__global__ __launch_bounds__(256) void moran_kernel(
    const float* __restrict__ txg, const float* __restrict__ tyg, float* __restrict__ out)
{
    extern __shared__ float smf[];
    float* st  = smf;
    float* sy  = st + NT*9;
    float* smu = sy + NT;
    int b  = blockIdx.x >> 4;
    int t0 = (blockIdx.x & 15) << 7;
    int tid = threadIdx.x;

    for (int i = tid; i < NT*XD; i += 256) st[(i>>3)*9 + (i&7)] = txg[(size_t)b*NT*XD + i];
    for (int i = tid; i < NT; i += 256) { sy[i] = tyg[b*NT + i]; smu[i] = out[b*NT + i]; }
    __syncthreads();
    for (int i = tid; i < NT; i += 256) {
        float n = 0.f;
        #pragma unroll
        for (int x = 0; x < XD; x++) { float v = st[i*9 + x]; n = fmaf(v, v, n); }
        st[i*9 + 8] = n;
    }
    __syncthreads();

    int warp = tid >> 5, lane = tid & 31;
    for (int tt = warp; tt < 128; tt += 8) {
        int t = t0 + tt;
        float tx[XD];
        #pragma unroll
        for (int x = 0; x < XD; x++) tx[x] = st[t*9 + x];
        float tn = st[t*9 + 8];

        float bd0=INFINITY,bd1=INFINITY,bd2=INFINITY,bd3=INFINITY,bd4=INFINITY;
        int   bi0=0,bi1=0,bi2=0,bi3=0,bi4=0;
        for (int c = lane; c < NT; c += 32) {
            if (c == t) continue;
            const float* p = &st[c*9];
            float dot = 0.f;
            #pragma unroll
            for (int x = 0; x < XD; x++) dot = fmaf(tx[x], p[x], dot);
            float d2 = tn + p[8] - 2.f*dot;
            d2 = fmaxf(d2, 0.f) + 1e-12f;
            if (d2 < bd4) {
                bd4 = d2; bi4 = c;
                if (bd4 < bd3) { float td=bd3; bd3=bd4; bd4=td; int ti=bi3; bi3=bi4; bi4=ti; }
                if (bd3 < bd2) { float td=bd2; bd2=bd3; bd3=td; int ti=bi2; bi2=bi3; bi3=ti; }
                if (bd2 < bd1) { float td=bd1; bd1=bd2; bd2=td; int ti=bi1; bi1=bi2; bi2=ti; }
                if (bd1 < bd0) { float td=bd0; bd0=bd1; bd1=td; int ti=bi0; bi0=bi1; bi1=ti; }
            }
        }
        float seld[5]; int seli[5];
        #pragma unroll
        for (int r = 0; r < 5; r++) {
            float rd = bd0; int ri = bi0; int rl = lane;
            #pragma unroll
            for (int o = 16; o; o >>= 1) {
                float od = __shfl_xor_sync(0xffffffffu, rd, o);
                int   oi = __shfl_xor_sync(0xffffffffu, ri, o);
                int   ol = __shfl_xor_sync(0xffffffffu, rl, o);
                if (od < rd || (od == rd && oi < ri)) { rd = od; ri = oi; rl = ol; }
            }
            seld[r] = rd; seli[r] = ri;
            if (lane == rl) {
                bd0=bd1; bi0=bi1; bd1=bd2; bi1=bi2; bd2=bd3; bi2=bi3;
                bd3=bd4; bi3=bi4; bd4=INFINITY; bi4=0x7fffffff;
            }
        }
        if (lane == 0) {
            float w[5], ws = 0.f;
            #pragma unroll
            for (int r = 0; r < 5; r++) { w[r] = __expf(-0.1f*sqrtf(seld[r])); ws += w[r]; }
            float inv = 1.f/ws;
            float ly = 0.f, lm = 0.f;
            #pragma unroll
            for (int r = 0; r < 5; r++) {
                float wr = w[r]*inv;
                ly = fmaf(wr, sy[seli[r]],  ly);
                lm = fmaf(wr, smu[seli[r]], lm);
            }
            size_t gt = (size_t)b*NT + t;
            out[2*(size_t)NTT + gt] = ly;
            out[3*(size_t)NTT + gt] = lm;
        }
    }
}

// ---------------- launch ----------------
extern "C" void kernel_launch(void* const* d_in, const int* in_sizes, int n_in,
                              void* d_out, int out_size)
{
    const float* cx   = (const float*)d_in[0];
    const float* cy   = (const float*)d_in[1];
    const float* txp  = (const float*)d_in[2];
    const float* typ  = (const float*)d_in[3];
    const float* Wge  = (const float*)d_in[4];
    const float* bge  = (const float*)d_in[5];
    const float* Wee  = (const float*)d_in[6];
    const float* bee  = (const float*)d_in[7];
    const float* Wp3  = (const float*)d_in[8];
    const float* bp3  = (const float*)d_in[9];
    const float* Wlin = (const float*)d_in[10];
    const float* blin = (const float*)d_in[11];
    const float* Wf1  = (const float*)d_in[12];
    const float* bf1  = (const float*)d_in[13];
    const float* Wf2  = (const float*)d_in[14];
    const float* bf2  = (const float*)d_in[15];
    const float* Wat  = (const float*)d_in[16];
    const float* bat  = (const float*)d_in[17];
    const float* Wgd  = (const float*)d_in[18];
    const float* bgd  = (const float*)d_in[19];
    const float* Wed  = (const float*)d_in[20];
    const float* bed  = (const float*)d_in[21];
    const float* Wd1  = (const float*)d_in[22];
    const float* bd1  = (const float*)d_in[23];
    const float* Wd2  = (const float*)d_in[24];
    const float* bd2  = (const float*)d_in[25];
    const float* Wd3  = (const float*)d_in[26];
    const float* bd3  = (const float*)d_in[27];
    float* out = (float*)d_out;

    float *p_gd;
    cudaGetSymbolAddress((void**)&p_gd, g_gd);
    __half *p_z, *p_fh, *p_zd, *p_zd2, *p_h1, *p_h2;
    cudaGetSymbolAddress((void**)&p_z,   g_z);
    cudaGetSymbolAddress((void**)&p_fh,  g_fh);
    cudaGetSymbolAddress((void**)&p_zd,  g_zd);
    cudaGetSymbolAddress((void**)&p_zd2, g_zd2);
    cudaGetSymbolAddress((void**)&p_h1,  g_h1);
    cudaGetSymbolAddress((void**)&p_h2,  g_h2);
    __half *wf1, *wf2, *wm, *wd1, *wd2;
    cudaGetSymbolAddress((void**)&wf1, g_wf1);
    cudaGetSymbolAddress((void**)&wf2, g_wf2);
    cudaGetSymbolAddress((void**)&wm,  g_wm);
    cudaGetSymbolAddress((void**)&wd1, g_wd1);
    cudaGetSymbolAddress((void**)&wd2, g_wd2);

    const int smem_t = (NC*9 + NE*9*HID + NE*HID + XD*HH + HH + XD*NE + NE)*4;
    const int smem_m = (NT*9 + NT + NT)*4;
    cudaFuncSetAttribute(target_kernel, cudaFuncAttributeMaxDynamicSharedMemorySize, smem_t);
    cudaFuncSetAttribute(moran_kernel,  cudaFuncAttributeMaxDynamicSharedMemorySize, smem_m);
    cudaFuncSetAttribute(mma_gemm,      cudaFuncAttributeMaxDynamicSharedMemorySize, SMEM_GEMM);

    PrepDesc pd0 = { Wf1, wf1, 512, 128, 512*128 };
    PrepDesc pd1 = { Wf2, wf2, 128, 256, 128*256 };
    PrepDesc pd2 = { Wed, wm,  384, 384, 4*384*384 };
    PrepDesc pd3 = { Wd1, wd1, 384, 256, 384*256 };
    PrepDesc pd4 = { Wd2, wd2, 256, 256, 256*256 };
    prep_all<<<dim3(160, 5), 256>>>(pd0, pd1, pd2, pd3, pd4);

    enc3_kernel<<<BSZ, 256>>>(cx, cy, Wp3, bp3, Wlin, blin);
    target_kernel<<<256, 256, smem_t>>>(cx, cy, txp, Wee, bee, Wge, bge, Wat, bat);
    // fps1: relu(z @ Wf1 + b)
    mma_gemm<<<dim3(256,1), 256, SMEM_GEMM>>>(p_z,   wf1, bf1, nullptr, p_fh,  512, 128, 0,   1, 1);
    // fps2: r = fh @ Wf2 + b -> zd[:,128:384]
    mma_gemm<<<dim3(256,2), 256, SMEM_GEMM>>>(p_fh,  wf2, bf2, nullptr, p_zd,  128, 384, 128, 1, 0);
    decgate_kernel<<<NTT/8, 256>>>(Wgd, bgd);
    // decoder MoE (gate-scaled A rows, accumulate over experts)
    mma_gemm<<<dim3(256,3), 256, SMEM_GEMM>>>(p_zd,  wm,  bed, p_gd,    p_zd2, 384, 384, 0,   4, 0);
    mma_gemm<<<dim3(256,2), 256, SMEM_GEMM>>>(p_zd2, wd1, bd1, nullptr, p_h1,  384, 256, 0,   1, 1);
    mma_gemm<<<dim3(256,2), 256, SMEM_GEMM>>>(p_h1,  wd2, bd2, nullptr, p_h2,  256, 256, 0,   1, 1);
    head_kernel<<<NTT/8, 256>>>(Wd3, bd3, out);
    moran_kernel<<<256, 256, smem_m>>>(txp, typ, out);
}